// round 5
// baseline (speedup 1.0000x reference)
#include <cuda_runtime.h>
#include <math.h>

// ---------------------------------------------------------------------------
// Problem constants
// ---------------------------------------------------------------------------
#define NA   256
#define HID  128
#define ACT  5
#define NH   4
#define DD   144
#define EE   576
#define HDH  144
#define OBS_RX 4
#define OBS_RY 2
#define WC_ROWS 145
#define NB   148          // persistent grid: 1 CTA per SM

#define KSPLIT 4          // stage-A K split (576/4 = 144 per chunk)
#define N_GEMM_ITEMS (3 * 3 * 9 * KSPLIT)       // 324
#define N_HEAD_ITEMS 9
#define N_OBS_ITEMS  8
#define N_POOL_ITEMS (N_GEMM_ITEMS + N_HEAD_ITEMS + N_OBS_ITEMS + 1)  // 342

// ---------------------------------------------------------------------------
// Device scratch
// ---------------------------------------------------------------------------
__device__ float    g_C[NA * DD];
__device__ unsigned g_mask[NA * 8];
__device__ float    g_WcP[KSPLIT][3][WC_ROWS * EE];   // partial combined weights
__device__ float    g_Q[3][NA * EE];
__device__ float    g_S[NH * NA * NA];
__device__ float    g_G[NA * EE];
__device__ float    g_cnt[NA];
__device__ float    g_Wfin[EE * 6];
__device__ float    g_bfin[6];

__device__ unsigned          g_ticket;     // dynamic work queue for stage A pool
__device__ unsigned          g_bar_count;
__device__ volatile unsigned g_bar_sense;

// ---------------------------------------------------------------------------
// Shared memory union
// ---------------------------------------------------------------------------
struct SmemGemm  { float As[2][16][68]; float Bs[2][16][68]; };
struct SmemAttn  { float w[NH * NA]; int Jl[NA]; int sn; };
struct SmemHead  { float W2[EE * 6]; };
struct SmemSetup { int px[NA]; int py[NA]; };
union  SmemU { SmemGemm g; SmemAttn a; SmemHead h; SmemSetup s; };

// ---------------------------------------------------------------------------
// Packed f32x2 helpers (sm_103a FFMA2)
// ---------------------------------------------------------------------------
typedef unsigned long long u64t;

__device__ __forceinline__ u64t pack2(float x) {
    u64t r;
    asm("mov.b64 %0, {%1, %1};" : "=l"(r) : "f"(x));
    return r;
}
__device__ __forceinline__ u64t fma2(u64t a, u64t b, u64t c) {
    u64t d;
    asm("fma.rn.f32x2 %0, %1, %2, %3;" : "=l"(d) : "l"(a), "l"(b), "l"(c));
    return d;
}
__device__ __forceinline__ float2 unpack2(u64t v) {
    float lo, hi;
    asm("mov.b64 {%0, %1}, %2;" : "=f"(lo), "=f"(hi) : "l"(v));
    return make_float2(lo, hi);
}

// 16-deep k-slab MMA: acc[i][0] covers n-cols (tx*4+0, tx*4+1),
//                     acc[i][1] covers n-cols (tx*4+2, tx*4+3)
__device__ __forceinline__ void mma16_f2(const float (*As)[68], const float (*Bs)[68],
                                         int ty, int tx, u64t acc[4][2])
{
#pragma unroll
    for (int kk = 0; kk < 16; ++kk) {
        const float4 av = *reinterpret_cast<const float4*>(&As[kk][ty * 4]);
        const u64t*  bp = reinterpret_cast<const u64t*>(&Bs[kk][0]);
        const u64t b0 = bp[tx * 2 + 0];
        const u64t b1 = bp[tx * 2 + 1];
        const u64t a0 = pack2(av.x), a1 = pack2(av.y);
        const u64t a2 = pack2(av.z), a3 = pack2(av.w);
        acc[0][0] = fma2(a0, b0, acc[0][0]); acc[0][1] = fma2(a0, b1, acc[0][1]);
        acc[1][0] = fma2(a1, b0, acc[1][0]); acc[1][1] = fma2(a1, b1, acc[1][1]);
        acc[2][0] = fma2(a2, b0, acc[2][0]); acc[2][1] = fma2(a2, b1, acc[2][1]);
        acc[3][0] = fma2(a3, b0, acc[3][0]); acc[3][1] = fma2(a3, b1, acc[3][1]);
    }
}

#define GRID_BAR()                                                        \
    do {                                                                  \
        __threadfence();                                                  \
        __syncthreads();                                                  \
        if (tid == 0) {                                                   \
            unsigned target = s_sense ^ 1u;                               \
            s_sense = target;                                             \
            unsigned aidx = atomicAdd(&g_bar_count, 1u);                  \
            if (aidx == (unsigned)(NB - 1)) {                             \
                g_bar_count = 0u;                                         \
                __threadfence();                                          \
                g_bar_sense = target;                                     \
            } else {                                                      \
                while (g_bar_sense != target) __nanosleep(64);            \
            }                                                             \
        }                                                                 \
        __syncthreads();                                                  \
        __threadfence();                                                  \
    } while (0)

// ---------------------------------------------------------------------------
__global__ __launch_bounds__(256)
void fused_kernel(const float* __restrict__ hid,   const float* __restrict__ act,
                  const int*   __restrict__ state,
                  const float* __restrict__ W_enc, const float* __restrict__ b_enc,
                  const float* __restrict__ Wq,  const float* __restrict__ bq,
                  const float* __restrict__ Wk,  const float* __restrict__ bk,
                  const float* __restrict__ Wv,  const float* __restrict__ bv,
                  const float* __restrict__ Wiq, const float* __restrict__ biq,
                  const float* __restrict__ Wik, const float* __restrict__ bik,
                  const float* __restrict__ Wiv, const float* __restrict__ biv,
                  const float* __restrict__ Wo,  const float* __restrict__ bo,
                  const float* __restrict__ W_O,
                  const float* __restrict__ W_val, const float* __restrict__ b_val,
                  const float* __restrict__ W_adv, const float* __restrict__ b_adv,
                  float* __restrict__ out)
{
    __shared__ SmemU sm;
    __shared__ unsigned s_sense;
    __shared__ unsigned s_item;
    const int tid = threadIdx.x;
    const int bx  = blockIdx.x;
    if (tid == 0) s_sense = 0u;

    const int tx  = tid & 15;
    const int ty  = tid >> 4;
    const int ma  = tid >> 2;
    const int ka  = (tid & 3) * 4;
    const int kb  = tid >> 4;
    const int nbv = (tid & 15) * 4;

    // =====================================================================
    // STAGE A: dynamic pool
    //   items 0..323   : combined-weight GEMM chunks (z, mtile, ntile, kslice)
    //   items 324..332 : head combine (64 Wfin rows each; item 324 also bfin)
    //   items 333..340 : obs encoder + action copy (32 agents each)
    //   item  341      : visibility mask
    // =====================================================================
    for (;;) {
        __syncthreads();
        if (tid == 0) s_item = atomicAdd(&g_ticket, 1u);
        __syncthreads();
        const unsigned item = s_item;
        if (item >= N_POOL_ITEMS) break;

        if (item < N_GEMM_ITEMS) {
            const int z  = item / 108;
            const int r  = item % 108;
            const int mt = r / 36;
            const int r2 = r % 36;
            const int nt = r2 / KSPLIT;
            const int ks = r2 % KSPLIT;
            const int m0 = mt * 64, n0 = nt * 64;
            const int kbase = ks * 144;

            const float* Az   = (z == 0) ? Wq  : (z == 1) ? Wk  : Wv;
            const float* brow = (z == 0) ? bq  : (z == 1) ? bk  : bv;
            const float* Bz   = (z == 0) ? Wiq : (z == 1) ? Wik : Wiv;
            const float* bi   = (z == 0) ? biq : (z == 1) ? bik : biv;
            float* Cd = &g_WcP[ks][z][0];

            const int rA = m0 + ma;
            const float* arp = (rA < DD) ? (Az + rA * EE)
                             : ((rA == DD) ? brow : nullptr);

            u64t acc[4][2] = {};
            float4 va, vb;
            va = arp ? *(const float4*)&arp[kbase + ka] : make_float4(0.f, 0.f, 0.f, 0.f);
            vb = *(const float4*)&Bz[(kbase + kb) * EE + n0 + nbv];
            sm.g.As[0][ka + 0][ma] = va.x; sm.g.As[0][ka + 1][ma] = va.y;
            sm.g.As[0][ka + 2][ma] = va.z; sm.g.As[0][ka + 3][ma] = va.w;
            sm.g.Bs[0][kb][nbv + 0] = vb.x; sm.g.Bs[0][kb][nbv + 1] = vb.y;
            sm.g.Bs[0][kb][nbv + 2] = vb.z; sm.g.Bs[0][kb][nbv + 3] = vb.w;
            __syncthreads();

            const int nk = 144 / 16;   // 9
            for (int it = 0; it < nk; ++it) {
                const int buf = it & 1;
                if (it + 1 < nk) {
                    const int k0 = kbase + (it + 1) * 16;
                    va = arp ? *(const float4*)&arp[k0 + ka] : make_float4(0.f, 0.f, 0.f, 0.f);
                    vb = *(const float4*)&Bz[(k0 + kb) * EE + n0 + nbv];
                }
                mma16_f2(sm.g.As[buf], sm.g.Bs[buf], ty, tx, acc);
                if (it + 1 < nk) {
                    const int nb2 = buf ^ 1;
                    sm.g.As[nb2][ka + 0][ma] = va.x; sm.g.As[nb2][ka + 1][ma] = va.y;
                    sm.g.As[nb2][ka + 2][ma] = va.z; sm.g.As[nb2][ka + 3][ma] = va.w;
                    sm.g.Bs[nb2][kb][nbv + 0] = vb.x; sm.g.Bs[nb2][kb][nbv + 1] = vb.y;
                    sm.g.Bs[nb2][kb][nbv + 2] = vb.z; sm.g.Bs[nb2][kb][nbv + 3] = vb.w;
                }
                __syncthreads();
            }
#pragma unroll
            for (int i = 0; i < 4; ++i) {
                const int m = m0 + ty * 4 + i;
                if (m >= WC_ROWS) continue;
                const float2 p0 = unpack2(acc[i][0]);
                const float2 p1 = unpack2(acc[i][1]);
                float v0 = p0.x, v1 = p0.y, v2 = p1.x, v3 = p1.y;
                const int n = n0 + tx * 4;
                if (ks == 0 && m == DD) {
                    v0 += bi[n + 0]; v1 += bi[n + 1];
                    v2 += bi[n + 2]; v3 += bi[n + 3];
                }
                Cd[m * EE + n + 0] = v0; Cd[m * EE + n + 1] = v1;
                Cd[m * EE + n + 2] = v2; Cd[m * EE + n + 3] = v3;
            }
        } else if (item < N_GEMM_ITEMS + N_HEAD_ITEMS) {
            // ---- head combine ----
            const int part = item - N_GEMM_ITEMS;
            for (int r = tid; r < EE; r += 256) {
                float a[6] = {};
                for (int k = 0; k < DD; ++k) {
                    const float w = W_O[r * DD + k];
                    a[0] += w * W_val[k];
#pragma unroll
                    for (int j = 0; j < ACT; ++j) a[1 + j] += w * W_adv[k * ACT + j];
                }
#pragma unroll
                for (int j = 0; j < 6; ++j) sm.h.W2[r * 6 + j] = a[j];
            }
            __syncthreads();
            if (tid < 64) {
                const int e = part * 64 + tid;
                float a[6] = {};
                for (int f = 0; f < EE; ++f) {
                    const float w = Wo[e * EE + f];
#pragma unroll
                    for (int j = 0; j < 6; ++j) a[j] += w * sm.h.W2[f * 6 + j];
                }
#pragma unroll
                for (int j = 0; j < 6; ++j) g_Wfin[e * 6 + j] = a[j];
            } else if (part == 0 && tid < 70) {
                const int j = tid - 64;
                float s = 0.f;
                for (int f = 0; f < EE; ++f) s += bo[f] * sm.h.W2[f * 6 + j];
                g_bfin[j] = s;
            }
        } else if (item < N_GEMM_ITEMS + N_HEAD_ITEMS + N_OBS_ITEMS) {
            // ---- obs encoder (32 agents) + action copy ----
            const int base = (item - N_GEMM_ITEMS - N_HEAD_ITEMS) * 32;
            const int ai   = base + (tid >> 3);
            const int tgrp = (tid & 7) * 2;
            float o0 = b_enc[tgrp], o1 = b_enc[tgrp + 1];
            for (int d = 0; d < HID; ++d) {
                const float hv = hid[ai * HID + d];
                o0 += hv * W_enc[d * 16 + tgrp];
                o1 += hv * W_enc[d * 16 + tgrp + 1];
            }
            g_C[ai * DD + tgrp]     = o0;
            g_C[ai * DD + tgrp + 1] = o1;
            const float4* act4 = (const float4*)act;
            for (int idx = tid; idx < 32 * 32; idx += 256) {
                const int row = idx >> 5, col = idx & 31;
                *(float4*)&g_C[(base + row) * DD + 16 + col * 4] =
                    act4[(base + row) * 32 + col];
            }
        } else {
            // ---- visibility mask ----
            const int i = tid;
            sm.s.px[i] = state[2 * i];
            sm.s.py[i] = state[2 * i + 1];
            __syncthreads();
            unsigned wbits[8] = {0, 0, 0, 0, 0, 0, 0, 0};
            const int xi = sm.s.px[i], yi = sm.s.py[i];
            for (int j = i + 1; j < NA; ++j) {
                const int dx = abs(xi - sm.s.px[j]);
                const int dy = abs(yi - sm.s.py[j]);
                if (dx <= OBS_RX && dy <= OBS_RY) wbits[j >> 5] |= (1u << (j & 31));
            }
#pragma unroll
            for (int t = 0; t < 8; ++t) g_mask[i * 8 + t] = wbits[t];
        }
    }
    GRID_BAR();

    // reset pool ticket for the next graph replay (no reader until then)
    if (bx == 0 && tid == 0) g_ticket = 0u;

    // =====================================================================
    // STAGE B: q,k,v = C_ext @ (sum_ks WcP) ;  108 tiles (3z x 4m x 9n)
    // =====================================================================
    if (bx < 108) {
        const int z  = bx / 36, r = bx % 36;
        const int m0 = (r / 9) * 64, n0 = (r % 9) * 64;
        const float* P0 = &g_WcP[0][z][0];
        const float* P1 = &g_WcP[1][z][0];
        const float* P2 = &g_WcP[2][z][0];
        const float* P3 = &g_WcP[3][z][0];
        float* Cd = &g_Q[z][0];

        u64t acc[4][2] = {};
        float4 va, w0, w1, w2, w3;
        va = *(const float4*)&g_C[(m0 + ma) * DD + ka];
        {
            const int off = kb * EE + n0 + nbv;
            w0 = *(const float4*)&P0[off]; w1 = *(const float4*)&P1[off];
            w2 = *(const float4*)&P2[off]; w3 = *(const float4*)&P3[off];
        }
        sm.g.As[0][ka + 0][ma] = va.x; sm.g.As[0][ka + 1][ma] = va.y;
        sm.g.As[0][ka + 2][ma] = va.z; sm.g.As[0][ka + 3][ma] = va.w;
        sm.g.Bs[0][kb][nbv + 0] = w0.x + w1.x + w2.x + w3.x;
        sm.g.Bs[0][kb][nbv + 1] = w0.y + w1.y + w2.y + w3.y;
        sm.g.Bs[0][kb][nbv + 2] = w0.z + w1.z + w2.z + w3.z;
        sm.g.Bs[0][kb][nbv + 3] = w0.w + w1.w + w2.w + w3.w;
        __syncthreads();

        const int nk = DD / 16;   // 9
        for (int it = 0; it < nk; ++it) {
            const int buf = it & 1;
            if (it + 1 < nk) {
                const int k0 = (it + 1) * 16;
                va = *(const float4*)&g_C[(m0 + ma) * DD + k0 + ka];
                const int off = (k0 + kb) * EE + n0 + nbv;
                w0 = *(const float4*)&P0[off]; w1 = *(const float4*)&P1[off];
                w2 = *(const float4*)&P2[off]; w3 = *(const float4*)&P3[off];
            }
            mma16_f2(sm.g.As[buf], sm.g.Bs[buf], ty, tx, acc);
            if (it + 1 < nk) {
                const int nb2 = buf ^ 1;
                sm.g.As[nb2][ka + 0][ma] = va.x; sm.g.As[nb2][ka + 1][ma] = va.y;
                sm.g.As[nb2][ka + 2][ma] = va.z; sm.g.As[nb2][ka + 3][ma] = va.w;
                sm.g.Bs[nb2][kb][nbv + 0] = w0.x + w1.x + w2.x + w3.x;
                sm.g.Bs[nb2][kb][nbv + 1] = w0.y + w1.y + w2.y + w3.y;
                sm.g.Bs[nb2][kb][nbv + 2] = w0.z + w1.z + w2.z + w3.z;
                sm.g.Bs[nb2][kb][nbv + 3] = w0.w + w1.w + w2.w + w3.w;
            }
            __syncthreads();
        }
#pragma unroll
        for (int i = 0; i < 4; ++i) {
            const int m = m0 + ty * 4 + i;
            const int n = n0 + tx * 4;
            const float2 p0 = unpack2(acc[i][0]);
            const float2 p1 = unpack2(acc[i][1]);
            const int bo4 = DD * EE + n;
            Cd[m * EE + n + 0] = p0.x + P0[bo4 + 0] + P1[bo4 + 0] + P2[bo4 + 0] + P3[bo4 + 0];
            Cd[m * EE + n + 1] = p0.y + P0[bo4 + 1] + P1[bo4 + 1] + P2[bo4 + 1] + P3[bo4 + 1];
            Cd[m * EE + n + 2] = p1.x + P0[bo4 + 2] + P1[bo4 + 2] + P2[bo4 + 2] + P3[bo4 + 2];
            Cd[m * EE + n + 3] = p1.y + P0[bo4 + 3] + P1[bo4 + 3] + P2[bo4 + 3] + P3[bo4 + 3];
        }
    }
    GRID_BAR();

    // =====================================================================
    // STAGE C: S[h] = scale * q2_h @ k2_h^T   (64 tiles)
    // =====================================================================
    if (bx < 64) {
        const int h  = bx >> 4;
        const int m0 = ((bx >> 2) & 3) * 64;
        const int n0 = (bx & 3) * 64;
        const float* A = &g_Q[0][0] + h * HDH;
        const float* B = &g_Q[1][0] + h * HDH;
        float* Cd = g_S + h * NA * NA;
        const float scale = 1.0f / 12.0f;

        u64t acc[4][2] = {};
        float4 va, vb;
        va = *(const float4*)&A[(m0 + ma) * EE + ka];
        vb = *(const float4*)&B[(n0 + ma) * EE + ka];
        sm.g.As[0][ka + 0][ma] = va.x; sm.g.As[0][ka + 1][ma] = va.y;
        sm.g.As[0][ka + 2][ma] = va.z; sm.g.As[0][ka + 3][ma] = va.w;
        sm.g.Bs[0][ka + 0][ma] = vb.x; sm.g.Bs[0][ka + 1][ma] = vb.y;
        sm.g.Bs[0][ka + 2][ma] = vb.z; sm.g.Bs[0][ka + 3][ma] = vb.w;
        __syncthreads();

        const int nk = HDH / 16;   // 9
        for (int it = 0; it < nk; ++it) {
            const int buf = it & 1;
            if (it + 1 < nk) {
                const int k0 = (it + 1) * 16;
                va = *(const float4*)&A[(m0 + ma) * EE + k0 + ka];
                vb = *(const float4*)&B[(n0 + ma) * EE + k0 + ka];
            }
            mma16_f2(sm.g.As[buf], sm.g.Bs[buf], ty, tx, acc);
            if (it + 1 < nk) {
                const int nb2 = buf ^ 1;
                sm.g.As[nb2][ka + 0][ma] = va.x; sm.g.As[nb2][ka + 1][ma] = va.y;
                sm.g.As[nb2][ka + 2][ma] = va.z; sm.g.As[nb2][ka + 3][ma] = va.w;
                sm.g.Bs[nb2][ka + 0][ma] = vb.x; sm.g.Bs[nb2][ka + 1][ma] = vb.y;
                sm.g.Bs[nb2][ka + 2][ma] = vb.z; sm.g.Bs[nb2][ka + 3][ma] = vb.w;
            }
            __syncthreads();
        }
#pragma unroll
        for (int i = 0; i < 4; ++i) {
            const int m = m0 + ty * 4 + i;
            const int n = n0 + tx * 4;
            const float2 p0 = unpack2(acc[i][0]);
            const float2 p1 = unpack2(acc[i][1]);
            Cd[m * NA + n + 0] = scale * p0.x;
            Cd[m * NA + n + 1] = scale * p0.y;
            Cd[m * NA + n + 2] = scale * p1.x;
            Cd[m * NA + n + 3] = scale * p1.y;
        }
    }
    GRID_BAR();

    // =====================================================================
    // STAGE D: per-agent masked softmax-sum + sparse context -> G, cnt
    // =====================================================================
    for (int i = bx; i < NA; i += NB) {
        for (int t = tid; t < NH * NA; t += 256) sm.a.w[t] = 0.f;
        if (tid == 0) {
            int n = 0;
            for (int t = 0; t < 8; ++t) {
                unsigned bits = g_mask[i * 8 + t];
                while (bits) {
                    const int b = __ffs(bits) - 1;
                    sm.a.Jl[n++] = t * 32 + b;
                    bits &= bits - 1;
                }
            }
            sm.a.sn = n;
            g_cnt[i] = (float)n;
        }
        __syncthreads();

        const int n = sm.a.sn;
        if (n == 0) {
            for (int e = tid; e < EE; e += 256) g_G[i * EE + e] = 0.f;
        } else {
            for (int p = tid; p < NH * n; p += 256) {
                const int h  = p & 3;
                const int jj = sm.a.Jl[p >> 2];
                const float* row = g_S + h * NA * NA + jj * NA;
                float m = -1e30f;
                for (int t = 0; t < n; ++t) m = fmaxf(m, row[sm.a.Jl[t]]);
                float sum = 0.f;
                for (int t = 0; t < n; ++t) sum += expf(row[sm.a.Jl[t]] - m);
                const float inv = 1.f / sum;
                for (int t = 0; t < n; ++t)
                    atomicAdd(&sm.a.w[h * NA + t], expf(row[sm.a.Jl[t]] - m) * inv);
            }
            __syncthreads();
            const float* v2 = &g_Q[2][0];
            for (int e = tid; e < EE; e += 256) {
                const int h = e / HDH;
                float acc = 0.f;
                for (int t = 0; t < n; ++t)
                    acc += sm.a.w[h * NA + t] * v2[sm.a.Jl[t] * EE + e];
                g_G[i * EE + e] = acc;
            }
        }
        __syncthreads();
    }
    GRID_BAR();

    // =====================================================================
    // STAGE E: warp-per-agent final head
    // =====================================================================
    {
        const int gw   = bx * 8 + (tid >> 5);
        const int lane = tid & 31;
        if (gw < NA) {
            const float* Gr = g_G + gw * EE;
            float a[6] = {};
            for (int d = lane; d < EE; d += 32) {
                const float gv = Gr[d];
                const float* Wr = g_Wfin + d * 6;
#pragma unroll
                for (int j = 0; j < 6; ++j) a[j] += gv * Wr[j];
            }
#pragma unroll
            for (int j = 0; j < 6; ++j)
#pragma unroll
                for (int o = 16; o > 0; o >>= 1)
                    a[j] += __shfl_xor_sync(0xffffffffu, a[j], o);
            const float c = g_cnt[gw];
            const float V = a[0] + c * g_bfin[0] + b_val[0];
            float A[ACT], mean = 0.f;
#pragma unroll
            for (int j = 0; j < ACT; ++j) {
                A[j] = a[1 + j] + c * g_bfin[1 + j] + b_adv[j];
                mean += A[j];
            }
            mean *= (1.f / ACT);
            if (lane < ACT) out[gw * ACT + lane] = V + A[lane] - mean;
        }
    }
}

// ---------------------------------------------------------------------------
// Launch
// ---------------------------------------------------------------------------
extern "C" void kernel_launch(void* const* d_in, const int* in_sizes, int n_in,
                              void* d_out, int out_size)
{
    const float *hid, *act, *W_enc, *b_enc, *Wq, *bq, *Wk, *bk, *Wv, *bv;
    const float *Wiq, *biq, *Wik, *bik, *Wiv, *biv, *Wo, *bo, *W_O;
    const float *W_val, *b_val, *W_adv, *b_adv;
    const int* state;

    if (n_in >= 3 && in_sizes[2] == 512) {
        hid   = (const float*)d_in[0];  act  = (const float*)d_in[1];
        state = (const int*)  d_in[2];
        W_enc = (const float*)d_in[3];  b_enc = (const float*)d_in[4];
        Wq  = (const float*)d_in[5];    bq  = (const float*)d_in[6];
        Wk  = (const float*)d_in[7];    bk  = (const float*)d_in[8];
        Wv  = (const float*)d_in[9];    bv  = (const float*)d_in[10];
        Wiq = (const float*)d_in[11];   biq = (const float*)d_in[12];
        Wik = (const float*)d_in[13];   bik = (const float*)d_in[14];
        Wiv = (const float*)d_in[15];   biv = (const float*)d_in[16];
        Wo  = (const float*)d_in[17];   bo  = (const float*)d_in[18];
        W_O = (const float*)d_in[19];
        W_val = (const float*)d_in[20]; b_val = (const float*)d_in[21];
        W_adv = (const float*)d_in[22]; b_adv = (const float*)d_in[23];
    } else {
        hid   = (const float*)d_in[0];  act  = (const float*)d_in[1];
        W_enc = (const float*)d_in[2];  b_enc = (const float*)d_in[3];
        Wq  = (const float*)d_in[4];    bq  = (const float*)d_in[5];
        Wk  = (const float*)d_in[6];    bk  = (const float*)d_in[7];
        Wv  = (const float*)d_in[8];    bv  = (const float*)d_in[9];
        Wiq = (const float*)d_in[10];   biq = (const float*)d_in[11];
        Wik = (const float*)d_in[12];   bik = (const float*)d_in[13];
        Wiv = (const float*)d_in[14];   biv = (const float*)d_in[15];
        Wo  = (const float*)d_in[16];   bo  = (const float*)d_in[17];
        W_O = (const float*)d_in[18];
        W_val = (const float*)d_in[19]; b_val = (const float*)d_in[20];
        W_adv = (const float*)d_in[21]; b_adv = (const float*)d_in[22];
        state = (const int*)  d_in[23];
    }

    fused_kernel<<<NB, 256>>>(hid, act, state, W_enc, b_enc,
                              Wq, bq, Wk, bk, Wv, bv,
                              Wiq, biq, Wik, bik, Wiv, biv,
                              Wo, bo, W_O, W_val, b_val, W_adv, b_adv,
                              (float*)d_out);
}

// round 6
// speedup vs baseline: 1.0165x; 1.0165x over previous
#include <cuda_runtime.h>
#include <math.h>

// ---------------------------------------------------------------------------
#define NA   256
#define HID  128
#define ACT  5
#define NH   4
#define DD   144
#define EE   576
#define HDH  144
#define OBS_RX 4
#define OBS_RY 2
#define WC_ROWS 145
#define NB   296              // 2 CTAs per SM

#define KSPLIT 4
#define N_GEMM_ITEMS (5 * 9 * 3 * KSPLIT)      // 540  (32x64 tiles)
#define N_HEAD_ITEMS 9
#define N_OBS_ITEMS  8
#define N_POOL_ITEMS (N_GEMM_ITEMS + N_HEAD_ITEMS + N_OBS_ITEMS + 1)   // 558

// ---------------------------------------------------------------------------
__device__ float    g_C[NA * DD];
__device__ unsigned g_mask[NA * 8];
__device__ float    g_WcP[KSPLIT][3][WC_ROWS * EE];
__device__ float    g_Q[3][NA * EE];
__device__ float    g_S[NH * NA * NA];
__device__ float    g_G[NA * EE];
__device__ float    g_cnt[NA];
__device__ float    g_Wfin[EE * 6];
__device__ float    g_bfin[6];

__device__ unsigned          g_ticket;
__device__ unsigned          g_bar_count;
__device__ volatile unsigned g_bar_sense;

// ---------------------------------------------------------------------------
struct SmemGemm  { float As[2][16][36]; float Bs[2][16][68]; };
struct SmemAttn  { float w[NH * NA]; int Jl[NA]; int sn; };
struct SmemHead  { float W2[EE * 6]; };
struct SmemSetup { int px[NA]; int py[NA]; };
union  SmemU { SmemGemm g; SmemAttn a; SmemHead h; SmemSetup s; };

// 32x64 tile microkernel: per-thread 2 rows x 4 cols, 16-deep k-slab
__device__ __forceinline__ void mma16_24(const float (*As)[36], const float (*Bs)[68],
                                         int ty, int tx, float acc[2][4])
{
#pragma unroll
    for (int kk = 0; kk < 16; ++kk) {
        const float2 a = *reinterpret_cast<const float2*>(&As[kk][ty * 2]);
        const float4 b = *reinterpret_cast<const float4*>(&Bs[kk][tx * 4]);
        acc[0][0] += a.x * b.x; acc[0][1] += a.x * b.y;
        acc[0][2] += a.x * b.z; acc[0][3] += a.x * b.w;
        acc[1][0] += a.y * b.x; acc[1][1] += a.y * b.y;
        acc[1][2] += a.y * b.z; acc[1][3] += a.y * b.w;
    }
}

#define GRID_BAR()                                                        \
    do {                                                                  \
        __threadfence();                                                  \
        __syncthreads();                                                  \
        if (tid == 0) {                                                   \
            unsigned target = s_sense ^ 1u;                               \
            s_sense = target;                                             \
            unsigned aidx = atomicAdd(&g_bar_count, 1u);                  \
            if (aidx == (unsigned)(NB - 1)) {                             \
                g_bar_count = 0u;                                         \
                __threadfence();                                          \
                g_bar_sense = target;                                     \
            } else {                                                      \
                while (g_bar_sense != target) __nanosleep(64);            \
            }                                                             \
        }                                                                 \
        __syncthreads();                                                  \
        __threadfence();                                                  \
    } while (0)

// ---------------------------------------------------------------------------
__global__ __launch_bounds__(256, 2)
void fused_kernel(const float* __restrict__ hid,   const float* __restrict__ act,
                  const int*   __restrict__ state,
                  const float* __restrict__ W_enc, const float* __restrict__ b_enc,
                  const float* __restrict__ Wq,  const float* __restrict__ bq,
                  const float* __restrict__ Wk,  const float* __restrict__ bk,
                  const float* __restrict__ Wv,  const float* __restrict__ bv,
                  const float* __restrict__ Wiq, const float* __restrict__ biq,
                  const float* __restrict__ Wik, const float* __restrict__ bik,
                  const float* __restrict__ Wiv, const float* __restrict__ biv,
                  const float* __restrict__ Wo,  const float* __restrict__ bo,
                  const float* __restrict__ W_O,
                  const float* __restrict__ W_val, const float* __restrict__ b_val,
                  const float* __restrict__ W_adv, const float* __restrict__ b_adv,
                  float* __restrict__ out)
{
    __shared__ SmemU sm;
    __shared__ unsigned s_sense;
    __shared__ unsigned s_item;
    const int tid = threadIdx.x;
    const int bx  = blockIdx.x;
    if (tid == 0) s_sense = 0u;

    // thread roles
    const int tx  = tid & 15;          // n quad (4 cols)
    const int ty  = tid >> 4;          // m pair (2 rows)
    const int ma  = tid >> 2;          // A-tile row (tid<128 -> 0..31)
    const int ka  = (tid & 3) * 4;     // A-tile k offset
    const int kb  = tid >> 4;          // B-tile k row
    const int nbv = (tid & 15) * 4;    // B-tile n offset
    const bool aload = (tid < 128);

    // =====================================================================
    // STAGE A pool:
    //   0..539   combined-weight GEMM (32x64 tile, 9 k-tiles)
    //   540..548 head combine   549..556 obs encoder   557 mask
    // =====================================================================
    for (;;) {
        __syncthreads();
        if (tid == 0) s_item = atomicAdd(&g_ticket, 1u);
        __syncthreads();
        const unsigned item = s_item;
        if (item >= N_POOL_ITEMS) break;

        if (item < N_GEMM_ITEMS) {
            const int z  = item / 180;
            const int r  = item % 180;
            const int mt = r / 36;
            const int r2 = r % 36;
            const int nt = r2 / KSPLIT;
            const int ks = r2 % KSPLIT;
            const int m0 = mt * 32, n0 = nt * 64;
            const int kbase = ks * 144;

            const float* Az   = (z == 0) ? Wq  : (z == 1) ? Wk  : Wv;
            const float* brow = (z == 0) ? bq  : (z == 1) ? bk  : bv;
            const float* Bz   = (z == 0) ? Wiq : (z == 1) ? Wik : Wiv;
            const float* bi   = (z == 0) ? biq : (z == 1) ? bik : biv;
            float* Cd = &g_WcP[ks][z][0];

            const int rA = m0 + ma;
            const float* arp = (rA < DD) ? (Az + rA * EE)
                             : ((rA == DD) ? brow : nullptr);

            float acc[2][4] = {};
            float4 va = make_float4(0.f, 0.f, 0.f, 0.f), vb;
            if (aload && arp) va = *(const float4*)&arp[kbase + ka];
            vb = *(const float4*)&Bz[(kbase + kb) * EE + n0 + nbv];
            if (aload) {
                sm.g.As[0][ka + 0][ma] = va.x; sm.g.As[0][ka + 1][ma] = va.y;
                sm.g.As[0][ka + 2][ma] = va.z; sm.g.As[0][ka + 3][ma] = va.w;
            }
            sm.g.Bs[0][kb][nbv + 0] = vb.x; sm.g.Bs[0][kb][nbv + 1] = vb.y;
            sm.g.Bs[0][kb][nbv + 2] = vb.z; sm.g.Bs[0][kb][nbv + 3] = vb.w;
            __syncthreads();

            for (int it = 0; it < 9; ++it) {
                const int buf = it & 1;
                if (it + 1 < 9) {
                    const int k0 = kbase + (it + 1) * 16;
                    va = make_float4(0.f, 0.f, 0.f, 0.f);
                    if (aload && arp) va = *(const float4*)&arp[k0 + ka];
                    vb = *(const float4*)&Bz[(k0 + kb) * EE + n0 + nbv];
                }
                mma16_24(sm.g.As[buf], sm.g.Bs[buf], ty, tx, acc);
                if (it + 1 < 9) {
                    const int nb2 = buf ^ 1;
                    if (aload) {
                        sm.g.As[nb2][ka + 0][ma] = va.x; sm.g.As[nb2][ka + 1][ma] = va.y;
                        sm.g.As[nb2][ka + 2][ma] = va.z; sm.g.As[nb2][ka + 3][ma] = va.w;
                    }
                    sm.g.Bs[nb2][kb][nbv + 0] = vb.x; sm.g.Bs[nb2][kb][nbv + 1] = vb.y;
                    sm.g.Bs[nb2][kb][nbv + 2] = vb.z; sm.g.Bs[nb2][kb][nbv + 3] = vb.w;
                }
                __syncthreads();
            }
#pragma unroll
            for (int i = 0; i < 2; ++i) {
                const int m = m0 + ty * 2 + i;
                if (m >= WC_ROWS) continue;
                const int n = n0 + tx * 4;
                float v0 = acc[i][0], v1 = acc[i][1], v2 = acc[i][2], v3 = acc[i][3];
                if (ks == 0 && m == DD) {
                    v0 += bi[n + 0]; v1 += bi[n + 1];
                    v2 += bi[n + 2]; v3 += bi[n + 3];
                }
                Cd[m * EE + n + 0] = v0; Cd[m * EE + n + 1] = v1;
                Cd[m * EE + n + 2] = v2; Cd[m * EE + n + 3] = v3;
            }
        } else if (item < N_GEMM_ITEMS + N_HEAD_ITEMS) {
            const int part = item - N_GEMM_ITEMS;
            for (int r = tid; r < EE; r += 256) {
                float a[6] = {};
                for (int k = 0; k < DD; ++k) {
                    const float w = W_O[r * DD + k];
                    a[0] += w * W_val[k];
#pragma unroll
                    for (int j = 0; j < ACT; ++j) a[1 + j] += w * W_adv[k * ACT + j];
                }
#pragma unroll
                for (int j = 0; j < 6; ++j) sm.h.W2[r * 6 + j] = a[j];
            }
            __syncthreads();
            if (tid < 64) {
                const int e = part * 64 + tid;
                float a[6] = {};
                for (int f = 0; f < EE; ++f) {
                    const float w = Wo[e * EE + f];
#pragma unroll
                    for (int j = 0; j < 6; ++j) a[j] += w * sm.h.W2[f * 6 + j];
                }
#pragma unroll
                for (int j = 0; j < 6; ++j) g_Wfin[e * 6 + j] = a[j];
            } else if (part == 0 && tid < 70) {
                const int j = tid - 64;
                float s = 0.f;
                for (int f = 0; f < EE; ++f) s += bo[f] * sm.h.W2[f * 6 + j];
                g_bfin[j] = s;
            }
            __syncthreads();
        } else if (item < N_GEMM_ITEMS + N_HEAD_ITEMS + N_OBS_ITEMS) {
            const int base = (item - N_GEMM_ITEMS - N_HEAD_ITEMS) * 32;
            const int ai   = base + (tid >> 3);
            const int tgrp = (tid & 7) * 2;
            float o0 = b_enc[tgrp], o1 = b_enc[tgrp + 1];
            for (int d = 0; d < HID; ++d) {
                const float hv = hid[ai * HID + d];
                o0 += hv * W_enc[d * 16 + tgrp];
                o1 += hv * W_enc[d * 16 + tgrp + 1];
            }
            g_C[ai * DD + tgrp]     = o0;
            g_C[ai * DD + tgrp + 1] = o1;
            const float4* act4 = (const float4*)act;
            for (int idx = tid; idx < 32 * 32; idx += 256) {
                const int row = idx >> 5, col = idx & 31;
                *(float4*)&g_C[(base + row) * DD + 16 + col * 4] =
                    act4[(base + row) * 32 + col];
            }
        } else {
            const int i = tid;
            sm.s.px[i] = state[2 * i];
            sm.s.py[i] = state[2 * i + 1];
            __syncthreads();
            unsigned wbits[8] = {0, 0, 0, 0, 0, 0, 0, 0};
            const int xi = sm.s.px[i], yi = sm.s.py[i];
            for (int j = i + 1; j < NA; ++j) {
                const int dx = abs(xi - sm.s.px[j]);
                const int dy = abs(yi - sm.s.py[j]);
                if (dx <= OBS_RX && dy <= OBS_RY) wbits[j >> 5] |= (1u << (j & 31));
            }
#pragma unroll
            for (int t = 0; t < 8; ++t) g_mask[i * 8 + t] = wbits[t];
            __syncthreads();
        }
    }
    GRID_BAR();

    if (bx == 0 && tid == 0) g_ticket = 0u;   // reset for next replay

    // =====================================================================
    // STAGE B: q,k,v = C @ (sum_ks WcP) + bias  ;  216 static 32x64 tiles
    // =====================================================================
    if (bx < 216) {
        const int z  = bx / 72;
        const int r  = bx % 72;
        const int m0 = (r / 9) * 32, n0 = (r % 9) * 64;
        const float* P0 = &g_WcP[0][z][0];
        const float* P1 = &g_WcP[1][z][0];
        const float* P2 = &g_WcP[2][z][0];
        const float* P3 = &g_WcP[3][z][0];
        float* Cd = &g_Q[z][0];

        float acc[2][4] = {};
        float4 va = make_float4(0.f, 0.f, 0.f, 0.f), w0, w1, w2, w3;
        if (aload) va = *(const float4*)&g_C[(m0 + ma) * DD + ka];
        {
            const int off = kb * EE + n0 + nbv;
            w0 = *(const float4*)&P0[off]; w1 = *(const float4*)&P1[off];
            w2 = *(const float4*)&P2[off]; w3 = *(const float4*)&P3[off];
        }
        if (aload) {
            sm.g.As[0][ka + 0][ma] = va.x; sm.g.As[0][ka + 1][ma] = va.y;
            sm.g.As[0][ka + 2][ma] = va.z; sm.g.As[0][ka + 3][ma] = va.w;
        }
        sm.g.Bs[0][kb][nbv + 0] = w0.x + w1.x + w2.x + w3.x;
        sm.g.Bs[0][kb][nbv + 1] = w0.y + w1.y + w2.y + w3.y;
        sm.g.Bs[0][kb][nbv + 2] = w0.z + w1.z + w2.z + w3.z;
        sm.g.Bs[0][kb][nbv + 3] = w0.w + w1.w + w2.w + w3.w;
        __syncthreads();

        for (int it = 0; it < 9; ++it) {
            const int buf = it & 1;
            if (it + 1 < 9) {
                const int k0 = (it + 1) * 16;
                if (aload) va = *(const float4*)&g_C[(m0 + ma) * DD + k0 + ka];
                const int off = (k0 + kb) * EE + n0 + nbv;
                w0 = *(const float4*)&P0[off]; w1 = *(const float4*)&P1[off];
                w2 = *(const float4*)&P2[off]; w3 = *(const float4*)&P3[off];
            }
            mma16_24(sm.g.As[buf], sm.g.Bs[buf], ty, tx, acc);
            if (it + 1 < 9) {
                const int nb2 = buf ^ 1;
                if (aload) {
                    sm.g.As[nb2][ka + 0][ma] = va.x; sm.g.As[nb2][ka + 1][ma] = va.y;
                    sm.g.As[nb2][ka + 2][ma] = va.z; sm.g.As[nb2][ka + 3][ma] = va.w;
                }
                sm.g.Bs[nb2][kb][nbv + 0] = w0.x + w1.x + w2.x + w3.x;
                sm.g.Bs[nb2][kb][nbv + 1] = w0.y + w1.y + w2.y + w3.y;
                sm.g.Bs[nb2][kb][nbv + 2] = w0.z + w1.z + w2.z + w3.z;
                sm.g.Bs[nb2][kb][nbv + 3] = w0.w + w1.w + w2.w + w3.w;
            }
            __syncthreads();
        }
#pragma unroll
        for (int i = 0; i < 2; ++i) {
            const int m = m0 + ty * 2 + i;
            const int n = n0 + tx * 4;
            const int bo4 = DD * EE + n;
#pragma unroll
            for (int j = 0; j < 4; ++j)
                Cd[m * EE + n + j] = acc[i][j] +
                    P0[bo4 + j] + P1[bo4 + j] + P2[bo4 + j] + P3[bo4 + j];
        }
    }
    GRID_BAR();

    // =====================================================================
    // STAGE C: S[h] = scale * q2_h @ k2_h^T  ;  128 static 32x64 tiles
    // =====================================================================
    if (bx < 128) {
        const int h  = bx / 32;
        const int r  = bx % 32;
        const int m0 = (r / 4) * 32, n0 = (r % 4) * 64;
        const float* A = &g_Q[0][0] + h * HDH;
        const float* B = &g_Q[1][0] + h * HDH;
        float* Cd = g_S + h * NA * NA;
        const float scale = 1.0f / 12.0f;

        const int nbr = tid >> 2;          // B row (agent) 0..63
        const int kc  = (tid & 3) * 4;     // B k offset

        float acc[2][4] = {};
        float4 va = make_float4(0.f, 0.f, 0.f, 0.f), vb;
        if (aload) va = *(const float4*)&A[(m0 + ma) * EE + ka];
        vb = *(const float4*)&B[(n0 + nbr) * EE + kc];
        if (aload) {
            sm.g.As[0][ka + 0][ma] = va.x; sm.g.As[0][ka + 1][ma] = va.y;
            sm.g.As[0][ka + 2][ma] = va.z; sm.g.As[0][ka + 3][ma] = va.w;
        }
        sm.g.Bs[0][kc + 0][nbr] = vb.x; sm.g.Bs[0][kc + 1][nbr] = vb.y;
        sm.g.Bs[0][kc + 2][nbr] = vb.z; sm.g.Bs[0][kc + 3][nbr] = vb.w;
        __syncthreads();

        for (int it = 0; it < 9; ++it) {
            const int buf = it & 1;
            if (it + 1 < 9) {
                const int k0 = (it + 1) * 16;
                if (aload) va = *(const float4*)&A[(m0 + ma) * EE + k0 + ka];
                vb = *(const float4*)&B[(n0 + nbr) * EE + k0 + kc];
            }
            mma16_24(sm.g.As[buf], sm.g.Bs[buf], ty, tx, acc);
            if (it + 1 < 9) {
                const int nb2 = buf ^ 1;
                if (aload) {
                    sm.g.As[nb2][ka + 0][ma] = va.x; sm.g.As[nb2][ka + 1][ma] = va.y;
                    sm.g.As[nb2][ka + 2][ma] = va.z; sm.g.As[nb2][ka + 3][ma] = va.w;
                }
                sm.g.Bs[nb2][kc + 0][nbr] = vb.x; sm.g.Bs[nb2][kc + 1][nbr] = vb.y;
                sm.g.Bs[nb2][kc + 2][nbr] = vb.z; sm.g.Bs[nb2][kc + 3][nbr] = vb.w;
            }
            __syncthreads();
        }
#pragma unroll
        for (int i = 0; i < 2; ++i) {
            const int m = m0 + ty * 2 + i;
            const int n = n0 + tx * 4;
#pragma unroll
            for (int j = 0; j < 4; ++j)
                Cd[m * NA + n + j] = scale * acc[i][j];
        }
    }
    GRID_BAR();

    // =====================================================================
    // STAGE D: per-agent masked softmax-sum + sparse context
    // =====================================================================
    if (bx < NA) {
        const int i = bx;
        for (int t = tid; t < NH * NA; t += 256) sm.a.w[t] = 0.f;
        if (tid == 0) {
            int n = 0;
            for (int t = 0; t < 8; ++t) {
                unsigned bits = g_mask[i * 8 + t];
                while (bits) {
                    const int b = __ffs(bits) - 1;
                    sm.a.Jl[n++] = t * 32 + b;
                    bits &= bits - 1;
                }
            }
            sm.a.sn = n;
            g_cnt[i] = (float)n;
        }
        __syncthreads();

        const int n = sm.a.sn;
        if (n == 0) {
            for (int e = tid; e < EE; e += 256) g_G[i * EE + e] = 0.f;
        } else {
            for (int p = tid; p < NH * n; p += 256) {
                const int h  = p & 3;
                const int jj = sm.a.Jl[p >> 2];
                const float* row = g_S + h * NA * NA + jj * NA;
                float m = -1e30f;
                for (int t = 0; t < n; ++t) m = fmaxf(m, row[sm.a.Jl[t]]);
                float sum = 0.f;
                for (int t = 0; t < n; ++t) sum += expf(row[sm.a.Jl[t]] - m);
                const float inv = 1.f / sum;
                for (int t = 0; t < n; ++t)
                    atomicAdd(&sm.a.w[h * NA + t], expf(row[sm.a.Jl[t]] - m) * inv);
            }
            __syncthreads();
            const float* v2 = &g_Q[2][0];
            for (int e = tid; e < EE; e += 256) {
                const int h = e / HDH;
                float acc = 0.f;
                for (int t = 0; t < n; ++t)
                    acc += sm.a.w[h * NA + t] * v2[sm.a.Jl[t] * EE + e];
                g_G[i * EE + e] = acc;
            }
        }
    }
    GRID_BAR();

    // =====================================================================
    // STAGE E: warp-per-agent final head
    // =====================================================================
    {
        const int gw   = bx * 8 + (tid >> 5);
        const int lane = tid & 31;
        if (gw < NA) {
            const float* Gr = g_G + gw * EE;
            float a[6] = {};
            for (int d = lane; d < EE; d += 32) {
                const float gv = Gr[d];
                const float* Wr = g_Wfin + d * 6;
#pragma unroll
                for (int j = 0; j < 6; ++j) a[j] += gv * Wr[j];
            }
#pragma unroll
            for (int j = 0; j < 6; ++j)
#pragma unroll
                for (int o = 16; o > 0; o >>= 1)
                    a[j] += __shfl_xor_sync(0xffffffffu, a[j], o);
            const float c = g_cnt[gw];
            const float V = a[0] + c * g_bfin[0] + b_val[0];
            float A[ACT], mean = 0.f;
#pragma unroll
            for (int j = 0; j < ACT; ++j) {
                A[j] = a[1 + j] + c * g_bfin[1 + j] + b_adv[j];
                mean += A[j];
            }
            mean *= (1.f / ACT);
            if (lane < ACT) out[gw * ACT + lane] = V + A[lane] - mean;
        }
    }
}

// ---------------------------------------------------------------------------
extern "C" void kernel_launch(void* const* d_in, const int* in_sizes, int n_in,
                              void* d_out, int out_size)
{
    const float *hid, *act, *W_enc, *b_enc, *Wq, *bq, *Wk, *bk, *Wv, *bv;
    const float *Wiq, *biq, *Wik, *bik, *Wiv, *biv, *Wo, *bo, *W_O;
    const float *W_val, *b_val, *W_adv, *b_adv;
    const int* state;

    if (n_in >= 3 && in_sizes[2] == 512) {
        hid   = (const float*)d_in[0];  act  = (const float*)d_in[1];
        state = (const int*)  d_in[2];
        W_enc = (const float*)d_in[3];  b_enc = (const float*)d_in[4];
        Wq  = (const float*)d_in[5];    bq  = (const float*)d_in[6];
        Wk  = (const float*)d_in[7];    bk  = (const float*)d_in[8];
        Wv  = (const float*)d_in[9];    bv  = (const float*)d_in[10];
        Wiq = (const float*)d_in[11];   biq = (const float*)d_in[12];
        Wik = (const float*)d_in[13];   bik = (const float*)d_in[14];
        Wiv = (const float*)d_in[15];   biv = (const float*)d_in[16];
        Wo  = (const float*)d_in[17];   bo  = (const float*)d_in[18];
        W_O = (const float*)d_in[19];
        W_val = (const float*)d_in[20]; b_val = (const float*)d_in[21];
        W_adv = (const float*)d_in[22]; b_adv = (const float*)d_in[23];
    } else {
        hid   = (const float*)d_in[0];  act  = (const float*)d_in[1];
        W_enc = (const float*)d_in[2];  b_enc = (const float*)d_in[3];
        Wq  = (const float*)d_in[4];    bq  = (const float*)d_in[5];
        Wk  = (const float*)d_in[6];    bk  = (const float*)d_in[7];
        Wv  = (const float*)d_in[8];    bv  = (const float*)d_in[9];
        Wiq = (const float*)d_in[10];   biq = (const float*)d_in[11];
        Wik = (const float*)d_in[12];   bik = (const float*)d_in[13];
        Wiv = (const float*)d_in[14];   biv = (const float*)d_in[15];
        Wo  = (const float*)d_in[16];   bo  = (const float*)d_in[17];
        W_O = (const float*)d_in[18];
        W_val = (const float*)d_in[19]; b_val = (const float*)d_in[20];
        W_adv = (const float*)d_in[21]; b_adv = (const float*)d_in[22];
        state = (const int*)  d_in[23];
    }

    fused_kernel<<<NB, 256>>>(hid, act, state, W_enc, b_enc,
                              Wq, bq, Wk, bk, Wv, bv,
                              Wiq, biq, Wik, bik, Wiv, biv,
                              Wo, bo, W_O, W_val, b_val, W_adv, b_adv,
                              (float*)d_out);
}